// round 6
// baseline (speedup 1.0000x reference)
#include <cuda_runtime.h>

// out = x @ y  (32x48 @ 48x32 fp32). The W0/W1/W2 one-hot LT matrices plus the
// roll-broadcast / roll-reduce pipeline in the reference compose to exactly
// this matmul (no circular-wrap aliasing); they are never read.
//
// R6: tail-trim probe. Kernel dur has been pinned ~4.2us across all structures
// (launch + un-ramped-clock round-trip floor). The only unprobed term is the
// post-load tail: R5 had 12 FMA + 2 dependent SHFL (~52cyc). Here: 2-way
// j-split -> 30 front-batched LDGs (extra issues hide under the round trip),
// 24 FMA in 6 chains, and only ONE shuffle in the tail.
//
// Grid 64 x 32. b -> i = b>>1 (row), kg = b&1 (16-k group).
// lane = k_local*2 + jseg: k = kg*16 + k_local, lane sums j in [jseg*24, +24).
// jseg==0 lanes (even) store 16 contiguous outputs per warp. No smem/barriers.

#define I_DIM 32
#define J_DIM 48
#define K_DIM 32

__global__ __launch_bounds__(32, 1)
void einsum_matmul_kernel(const float* __restrict__ x,
                          const float* __restrict__ y,
                          float* __restrict__ out) {
    const int b = blockIdx.x;            // 0..63
    const int i = b >> 1;                // output row 0..31
    const int kg = b & 1;                // k-group 0..1

    const int lane = threadIdx.x;        // 0..31
    const int k_local = lane >> 1;       // 0..15
    const int jseg = lane & 1;           // 0..1
    const int k = kg * 16 + k_local;     // 0..31
    const int j0 = jseg * 24;            // j base for this lane

    // Store address ready early (off the post-shuffle critical path).
    float* __restrict__ op = out + i * K_DIM + k;

    // x row slice: 24 floats, 16B-aligned (i*48 and jseg*24 both mult of 4).
    const float4* __restrict__ x4 = (const float4*)(x + i * J_DIM + j0);
    float4 xa = __ldg(&x4[0]);
    float4 xb = __ldg(&x4[1]);
    float4 xc = __ldg(&x4[2]);
    float4 xd = __ldg(&x4[3]);
    float4 xe = __ldg(&x4[4]);
    float4 xf = __ldg(&x4[5]);

    const float* __restrict__ yp = y + j0 * K_DIM + k;

    // 24 independent y loads, all front-batched under one round trip.
    float y0  = __ldg(&yp[ 0 * K_DIM]);
    float y1  = __ldg(&yp[ 1 * K_DIM]);
    float y2  = __ldg(&yp[ 2 * K_DIM]);
    float y3  = __ldg(&yp[ 3 * K_DIM]);
    float y4  = __ldg(&yp[ 4 * K_DIM]);
    float y5  = __ldg(&yp[ 5 * K_DIM]);
    float y6  = __ldg(&yp[ 6 * K_DIM]);
    float y7  = __ldg(&yp[ 7 * K_DIM]);
    float y8  = __ldg(&yp[ 8 * K_DIM]);
    float y9  = __ldg(&yp[ 9 * K_DIM]);
    float y10 = __ldg(&yp[10 * K_DIM]);
    float y11 = __ldg(&yp[11 * K_DIM]);
    float y12 = __ldg(&yp[12 * K_DIM]);
    float y13 = __ldg(&yp[13 * K_DIM]);
    float y14 = __ldg(&yp[14 * K_DIM]);
    float y15 = __ldg(&yp[15 * K_DIM]);
    float y16 = __ldg(&yp[16 * K_DIM]);
    float y17 = __ldg(&yp[17 * K_DIM]);
    float y18 = __ldg(&yp[18 * K_DIM]);
    float y19 = __ldg(&yp[19 * K_DIM]);
    float y20 = __ldg(&yp[20 * K_DIM]);
    float y21 = __ldg(&yp[21 * K_DIM]);
    float y22 = __ldg(&yp[22 * K_DIM]);
    float y23 = __ldg(&yp[23 * K_DIM]);

    // 6 independent accumulator chains, 4 FMAs deep each.
    float a0 = 0.0f, a1 = 0.0f, a2 = 0.0f, a3 = 0.0f, a4 = 0.0f, a5 = 0.0f;
    a0 = fmaf(xa.x, y0,  a0);
    a1 = fmaf(xa.y, y1,  a1);
    a2 = fmaf(xa.z, y2,  a2);
    a3 = fmaf(xa.w, y3,  a3);
    a4 = fmaf(xb.x, y4,  a4);
    a5 = fmaf(xb.y, y5,  a5);
    a0 = fmaf(xb.z, y6,  a0);
    a1 = fmaf(xb.w, y7,  a1);
    a2 = fmaf(xc.x, y8,  a2);
    a3 = fmaf(xc.y, y9,  a3);
    a4 = fmaf(xc.z, y10, a4);
    a5 = fmaf(xc.w, y11, a5);
    a0 = fmaf(xd.x, y12, a0);
    a1 = fmaf(xd.y, y13, a1);
    a2 = fmaf(xd.z, y14, a2);
    a3 = fmaf(xd.w, y15, a3);
    a4 = fmaf(xe.x, y16, a4);
    a5 = fmaf(xe.y, y17, a5);
    a0 = fmaf(xe.z, y18, a0);
    a1 = fmaf(xe.w, y19, a1);
    a2 = fmaf(xf.x, y20, a2);
    a3 = fmaf(xf.y, y21, a3);
    a4 = fmaf(xf.z, y22, a4);
    a5 = fmaf(xf.w, y23, a5);

    float acc = ((a0 + a1) + (a2 + a3)) + (a4 + a5);

    // Single shuffle: partner lane (jseg^1) holds the other half of j.
    acc += __shfl_xor_sync(0xFFFFFFFFu, acc, 1);

    if (jseg == 0) {
        *op = acc;   // even lanes: 16 contiguous floats per warp
    }
}

extern "C" void kernel_launch(void* const* d_in, const int* in_sizes, int n_in,
                              void* d_out, int out_size) {
    const float* x = (const float*)d_in[0];
    const float* y = (const float*)d_in[1];
    float* out = (float*)d_out;
    einsum_matmul_kernel<<<64, 32>>>(x, y, out);
}

// round 7
// speedup vs baseline: 1.0105x; 1.0105x over previous
#include <cuda_runtime.h>

// out = x @ y  (32x48 @ 48x32 fp32). The W0/W1/W2 one-hot LT matrices plus the
// roll-broadcast / roll-reduce pipeline in the reference compose to exactly
// this matmul (no circular-wrap aliasing); they are never read.
//
// R7 = R5 (best-measured: kernel 4.16us, bench 5.12us). Six structural
// variants (R1-R6) pinned kernel dur at 4.16-5.41us with all pipes <1% and
// issue ~3% -> the floor is launch + one un-ramped-clock memory round trip;
// bench-level spread is ~±0.6us replay noise. This config minimizes the
// measured critical path: 128 CTAs x 32 threads, 15 front-batched LDGs and
// 12 FMAs per thread, 2-shuffle butterfly tail, no smem, no barriers.
//
// Layout: blockIdx b -> i = b>>2 (row), kg = b&3 (8-k group).
// lane = k_local*4 + jseg: lane sums j in [jseg*12, jseg*12+12).

#define I_DIM 32
#define J_DIM 48
#define K_DIM 32

__global__ __launch_bounds__(32, 1)
void einsum_matmul_kernel(const float* __restrict__ x,
                          const float* __restrict__ y,
                          float* __restrict__ out) {
    const int b = blockIdx.x;          // 0..127
    const int i = b >> 2;              // output row 0..31
    const int kg = b & 3;              // k-group 0..3

    const int lane = threadIdx.x;      // 0..31
    const int k_local = lane >> 2;     // 0..7
    const int jseg = lane & 3;         // 0..3
    const int k = kg * 8 + k_local;    // 0..31
    const int j0 = jseg * 12;          // j base for this lane

    // Store address ready early (off the post-shuffle critical path).
    float* __restrict__ op = out + i * K_DIM + k;

    // x row slice: 12 floats, 16B-aligned (i*48 and jseg*12 both mult of 4).
    const float4* __restrict__ x4 = (const float4*)(x + i * J_DIM + j0);
    float4 xa = __ldg(&x4[0]);
    float4 xb = __ldg(&x4[1]);
    float4 xc = __ldg(&x4[2]);

    const float* __restrict__ yp = y + j0 * K_DIM + k;

    // 12 independent y loads (front-batched by ptxas), 3 accumulators.
    float y0  = __ldg(&yp[0 * K_DIM]);
    float y1  = __ldg(&yp[1 * K_DIM]);
    float y2  = __ldg(&yp[2 * K_DIM]);
    float y3  = __ldg(&yp[3 * K_DIM]);
    float y4  = __ldg(&yp[4 * K_DIM]);
    float y5  = __ldg(&yp[5 * K_DIM]);
    float y6  = __ldg(&yp[6 * K_DIM]);
    float y7  = __ldg(&yp[7 * K_DIM]);
    float y8  = __ldg(&yp[8 * K_DIM]);
    float y9  = __ldg(&yp[9 * K_DIM]);
    float y10 = __ldg(&yp[10 * K_DIM]);
    float y11 = __ldg(&yp[11 * K_DIM]);

    float a0 = 0.0f, a1 = 0.0f, a2 = 0.0f;
    a0 = fmaf(xa.x, y0, a0);
    a1 = fmaf(xa.y, y1, a1);
    a2 = fmaf(xa.z, y2, a2);
    a0 = fmaf(xa.w, y3, a0);
    a1 = fmaf(xb.x, y4, a1);
    a2 = fmaf(xb.y, y5, a2);
    a0 = fmaf(xb.z, y6, a0);
    a1 = fmaf(xb.w, y7, a1);
    a2 = fmaf(xc.x, y8, a2);
    a0 = fmaf(xc.y, y9, a0);
    a1 = fmaf(xc.z, y10, a1);
    a2 = fmaf(xc.w, y11, a2);

    float acc = (a0 + a1) + a2;

    // Butterfly reduce over the 4 jseg lanes (consecutive lanes).
    acc += __shfl_xor_sync(0xFFFFFFFFu, acc, 1);
    acc += __shfl_xor_sync(0xFFFFFFFFu, acc, 2);

    if (jseg == 0) {
        *op = acc;
    }
}

extern "C" void kernel_launch(void* const* d_in, const int* in_sizes, int n_in,
                              void* d_out, int out_size) {
    const float* x = (const float*)d_in[0];
    const float* y = (const float*)d_in[1];
    float* out = (float*)d_out;
    einsum_matmul_kernel<<<128, 32>>>(x, y, out);
}

// round 8
// speedup vs baseline: 1.2075x; 1.1950x over previous
#include <cuda_runtime.h>

// out = x @ y  (32x48 @ 48x32 fp32). The W0/W1/W2 one-hot LT matrices plus the
// roll-broadcast / roll-reduce pipeline in the reference compose to exactly
// this matmul (no circular-wrap aliasing); they are never read.
//
// R8 = R5/R7 verbatim (best-measured config; terminal). Session evidence:
// kernel dur is pinned at 4.16-4.64us across 6 structural variants, and a
// byte-identical resubmission (R7) showed ±0.3us kernel / ±1us bench noise —
// all variant deltas are inside noise. Floor = launch front-end + L2-warm
// round trip at replay-idle clocks (issue ~3%, all pipes ~0%). This config:
// 128 CTAs x 32 threads, 15 front-batched LDGs + 12 FMAs per thread,
// 2-shuffle butterfly tail, no smem, no barriers.
//
// Layout: blockIdx b -> i = b>>2 (row), kg = b&3 (8-k group).
// lane = k_local*4 + jseg: lane sums j in [jseg*12, jseg*12+12).

#define I_DIM 32
#define J_DIM 48
#define K_DIM 32

__global__ __launch_bounds__(32, 1)
void einsum_matmul_kernel(const float* __restrict__ x,
                          const float* __restrict__ y,
                          float* __restrict__ out) {
    const int b = blockIdx.x;          // 0..127
    const int i = b >> 2;              // output row 0..31
    const int kg = b & 3;              // k-group 0..3

    const int lane = threadIdx.x;      // 0..31
    const int k_local = lane >> 2;     // 0..7
    const int jseg = lane & 3;         // 0..3
    const int k = kg * 8 + k_local;    // 0..31
    const int j0 = jseg * 12;          // j base for this lane

    // Store address ready early (off the post-shuffle critical path).
    float* __restrict__ op = out + i * K_DIM + k;

    // x row slice: 12 floats, 16B-aligned (i*48 and jseg*12 both mult of 4).
    const float4* __restrict__ x4 = (const float4*)(x + i * J_DIM + j0);
    float4 xa = __ldg(&x4[0]);
    float4 xb = __ldg(&x4[1]);
    float4 xc = __ldg(&x4[2]);

    const float* __restrict__ yp = y + j0 * K_DIM + k;

    // 12 independent y loads (front-batched by ptxas), 3 accumulators.
    float y0  = __ldg(&yp[0 * K_DIM]);
    float y1  = __ldg(&yp[1 * K_DIM]);
    float y2  = __ldg(&yp[2 * K_DIM]);
    float y3  = __ldg(&yp[3 * K_DIM]);
    float y4  = __ldg(&yp[4 * K_DIM]);
    float y5  = __ldg(&yp[5 * K_DIM]);
    float y6  = __ldg(&yp[6 * K_DIM]);
    float y7  = __ldg(&yp[7 * K_DIM]);
    float y8  = __ldg(&yp[8 * K_DIM]);
    float y9  = __ldg(&yp[9 * K_DIM]);
    float y10 = __ldg(&yp[10 * K_DIM]);
    float y11 = __ldg(&yp[11 * K_DIM]);

    float a0 = 0.0f, a1 = 0.0f, a2 = 0.0f;
    a0 = fmaf(xa.x, y0, a0);
    a1 = fmaf(xa.y, y1, a1);
    a2 = fmaf(xa.z, y2, a2);
    a0 = fmaf(xa.w, y3, a0);
    a1 = fmaf(xb.x, y4, a1);
    a2 = fmaf(xb.y, y5, a2);
    a0 = fmaf(xb.z, y6, a0);
    a1 = fmaf(xb.w, y7, a1);
    a2 = fmaf(xc.x, y8, a2);
    a0 = fmaf(xc.y, y9, a0);
    a1 = fmaf(xc.z, y10, a1);
    a2 = fmaf(xc.w, y11, a2);

    float acc = (a0 + a1) + a2;

    // Butterfly reduce over the 4 jseg lanes (consecutive lanes).
    acc += __shfl_xor_sync(0xFFFFFFFFu, acc, 1);
    acc += __shfl_xor_sync(0xFFFFFFFFu, acc, 2);

    if (jseg == 0) {
        *op = acc;
    }
}

extern "C" void kernel_launch(void* const* d_in, const int* in_sizes, int n_in,
                              void* d_out, int out_size) {
    const float* x = (const float*)d_in[0];
    const float* y = (const float*)d_in[1];
    float* out = (float*)d_out;
    einsum_matmul_kernel<<<128, 32>>>(x, y, out);
}